// round 13
// baseline (speedup 1.0000x reference)
#include <cuda_runtime.h>
#include <cuda_fp16.h>
#include <cstdint>

#define NN 100000
#define NE 1600000
#define FD 128
#define NG 512
#define NC 10
#define NL 5
#define BN_EPS 1e-5f
#define SCAN_B 98                  // ceil(NN/1024)
#define LDH 68                     // padded smem stride (uint32 = 2 halves)
#define MT 128                     // GEMM M-tile
#define GB1 ((NN + MT - 1) / MT)   // 782 GEMM blocks

// ---------------- scratch (device globals; no allocs allowed) ----------------
__device__ float    g_P[NN * FD];        // fp32 output of last layer (pooling)
__device__ __half   g_Q[NN * FD];        // GEMM1 output (fp16, pre-BN)
__device__ __half   g_R[NN * FD];        // agg output (fp16)
__device__ __half   g_H[NN * FD];        // fp16 features for gather
__device__ __half   g_WT[10 * FD * FD];  // pre-transposed fp16 weights [mat][n][k]
__device__ float    g_psum[GB1 * FD];
__device__ float    g_psq[GB1 * FD];
__device__ float    g_scale[FD];
__device__ float    g_shift[FD];
__device__ unsigned g_ticket[NL];
__device__ int      g_cnt[NN];
__device__ int      g_off[NN + 1];
__device__ int      g_cur[NN];
__device__ int      g_csr[NE];
__device__ int      g_bsum[SCAN_B];
__device__ int      g_is64;

__device__ __forceinline__ int load_idx(const void* p, long long i) {
    if (g_is64) return (int)((const long long*)p)[i];
    return ((const int*)p)[i];
}

// ---------------- launch 0: zero counts/tickets + x->fp16 + width detect ------
__global__ void zero_prep_kernel(const unsigned* ei_words,
                                 const float2* __restrict__ x,
                                 __half2* __restrict__ h) {
    int i = blockIdx.x * 256 + threadIdx.x;
    if (i < NN * FD / 2) {
        float2 v = x[i];
        h[i] = __floats2half2_rn(v.x, v.y);
    }
    if (i < NN) g_cnt[i] = 0;
    if (i < NL) g_ticket[i] = 0u;
    if (i == 0) {
        int is64 = 1;
        for (int k = 1; k < 64; k++) {
            if (ei_words[2 * k + 1] != 0u) { is64 = 0; break; }
        }
        g_is64 = is64;
    }
}

// ---------------- launch 1: degree count + W transpose->fp16 -------------------
__global__ void count_kernel(const void* ei,
                             const float* __restrict__ W1,
                             const float* __restrict__ W2) {
    int b = blockIdx.x;
    if (b < NE / 256) {
        int e = b * 256 + threadIdx.x;
        int d = load_idx(ei, (long long)NE + e);
        atomicAdd(&g_cnt[d], 1);
    } else {
        int wb = b - NE / 256;              // 0..159
        int m = wb >> 4, s = wb & 15;
        const float* W = (m < 5) ? W1 + (size_t)m * FD * FD
                                 : W2 + (size_t)(m - 5) * FD * FD;
        int task = s * 256 + threadIdx.x;   // 0..4095 (4 k-values at one n)
        int n = task >> 5, k0 = (task & 31) * 4;
        __half2 p0 = __floats2half2_rn(__ldg(&W[(k0 + 0) * 128 + n]),
                                       __ldg(&W[(k0 + 1) * 128 + n]));
        __half2 p1 = __floats2half2_rn(__ldg(&W[(k0 + 2) * 128 + n]),
                                       __ldg(&W[(k0 + 3) * 128 + n]));
        uint2 o;
        o.x = *reinterpret_cast<unsigned*>(&p0);
        o.y = *reinterpret_cast<unsigned*>(&p1);
        *(uint2*)&g_WT[(size_t)m * 16384 + n * 128 + k0] = o;
    }
}

__global__ void scan_reduce_kernel() {
    int i = blockIdx.x * 1024 + threadIdx.x;
    int v = (i < NN) ? g_cnt[i] : 0;
    __shared__ int ws[32];
    int lane = threadIdx.x & 31, wid = threadIdx.x >> 5;
    #pragma unroll
    for (int d = 16; d > 0; d >>= 1) v += __shfl_down_sync(0xffffffffu, v, d);
    if (lane == 0) ws[wid] = v;
    __syncthreads();
    if (wid == 0) {
        int t = ws[lane];
        #pragma unroll
        for (int d = 16; d > 0; d >>= 1) t += __shfl_down_sync(0xffffffffu, t, d);
        if (lane == 0) g_bsum[blockIdx.x] = t;
    }
}

// block-local scan + serial per-block prefix of g_bsum
__global__ void scan_final_kernel() {
    __shared__ int wsum[32];
    __shared__ int carry;
    int tid = threadIdx.x, lane = tid & 31, wid = tid >> 5;
    if (tid == 0) {
        int acc = 0;
        for (int j = 0; j < blockIdx.x; j++) acc += g_bsum[j];
        carry = acc;
        if (blockIdx.x == SCAN_B - 1) {
            int tot = acc;
            for (int j = blockIdx.x; j < SCAN_B; j++) tot += g_bsum[j];
            g_off[NN] = tot;
        }
    }
    int i = blockIdx.x * 1024 + tid;
    int v = (i < NN) ? g_cnt[i] : 0;
    int incl = v;
    #pragma unroll
    for (int d = 1; d < 32; d <<= 1) {
        int t = __shfl_up_sync(0xffffffffu, incl, d);
        if (lane >= d) incl += t;
    }
    if (lane == 31) wsum[wid] = incl;
    __syncthreads();
    if (wid == 0) {
        int wv = wsum[lane];
        int wincl = wv;
        #pragma unroll
        for (int d = 1; d < 32; d <<= 1) {
            int t = __shfl_up_sync(0xffffffffu, wincl, d);
            if (lane >= d) wincl += t;
        }
        wsum[lane] = wincl - wv;
    }
    __syncthreads();
    if (i < NN) {
        int off = carry + wsum[wid] + incl - v;
        g_off[i] = off;
        g_cur[i] = off;
    }
}

__global__ void fill_kernel(const void* ei) {
    int e = blockIdx.x * blockDim.x + threadIdx.x;
    if (e < NE) {
        int s = load_idx(ei, e);
        int d = load_idx(ei, (long long)NE + e);
        int pos = atomicAdd(&g_cur[d], 1);
        g_csr[pos] = s;
    }
}

// ---------------- fp16 mma helper ----------------
__device__ __forceinline__ void mma_f16(float* c, const unsigned* a, const unsigned* b) {
    asm volatile(
        "mma.sync.aligned.m16n8k16.row.col.f32.f16.f16.f32 "
        "{%0,%1,%2,%3}, {%4,%5,%6,%7}, {%8,%9}, {%0,%1,%2,%3};"
        : "+f"(c[0]), "+f"(c[1]), "+f"(c[2]), "+f"(c[3])
        : "r"(a[0]), "r"(a[1]), "r"(a[2]), "r"(a[3]), "r"(b[0]), "r"(b[1]));
}

// ---------------- edge aggregation (fp16 in, HADD2 trees, fp32 acc) ----------
__device__ __forceinline__ float4 h4_to_f4(uint2 u) {
    __half2 h0 = *(__half2*)&u.x;
    __half2 h1 = *(__half2*)&u.y;
    float2 f0 = __half22float2(h0);
    float2 f1 = __half22float2(h1);
    return make_float4(f0.x, f0.y, f1.x, f1.y);
}

// 2-level fp16 tree over 4 rows; fp32 carry into acc
__device__ __forceinline__ void tree4_acc(float4& acc, uint2 u0, uint2 u1,
                                          uint2 u2, uint2 u3) {
    __half2 plo = __hadd2(__hadd2(*(__half2*)&u0.x, *(__half2*)&u1.x),
                          __hadd2(*(__half2*)&u2.x, *(__half2*)&u3.x));
    __half2 phi = __hadd2(__hadd2(*(__half2*)&u0.y, *(__half2*)&u1.y),
                          __hadd2(*(__half2*)&u2.y, *(__half2*)&u3.y));
    float2 flo = __half22float2(plo);
    float2 fhi = __half22float2(phi);
    acc.x += flo.x; acc.y += flo.y; acc.z += fhi.x; acc.w += fhi.y;
}

__global__ __launch_bounds__(256) void agg_kernel(const __half* __restrict__ xh,
                                                  __half* __restrict__ out) {
    int w = (blockIdx.x * blockDim.x + threadIdx.x) >> 5;
    int lane = threadIdx.x & 31;
    if (w >= NN) return;
    const uint2* xv = (const uint2*)xh;       // 32 uint2 per row (128 halves)
    float4 acc = h4_to_f4(__ldg(&xv[(size_t)w * 32 + lane]));
    int s = g_off[w], e = g_off[w + 1];
    int i = s;
    for (; i + 8 <= e; i += 8) {              // MLP-8: 8 rows in flight
        int n0 = __ldg(&g_csr[i + 0]);
        int n1 = __ldg(&g_csr[i + 1]);
        int n2 = __ldg(&g_csr[i + 2]);
        int n3 = __ldg(&g_csr[i + 3]);
        int n4 = __ldg(&g_csr[i + 4]);
        int n5 = __ldg(&g_csr[i + 5]);
        int n6 = __ldg(&g_csr[i + 6]);
        int n7 = __ldg(&g_csr[i + 7]);
        uint2 u0 = __ldg(&xv[(size_t)n0 * 32 + lane]);
        uint2 u1 = __ldg(&xv[(size_t)n1 * 32 + lane]);
        uint2 u2 = __ldg(&xv[(size_t)n2 * 32 + lane]);
        uint2 u3 = __ldg(&xv[(size_t)n3 * 32 + lane]);
        uint2 u4 = __ldg(&xv[(size_t)n4 * 32 + lane]);
        uint2 u5 = __ldg(&xv[(size_t)n5 * 32 + lane]);
        uint2 u6 = __ldg(&xv[(size_t)n6 * 32 + lane]);
        uint2 u7 = __ldg(&xv[(size_t)n7 * 32 + lane]);
        tree4_acc(acc, u0, u1, u2, u3);
        tree4_acc(acc, u4, u5, u6, u7);
    }
    for (; i + 4 <= e; i += 4) {
        int n0 = __ldg(&g_csr[i + 0]);
        int n1 = __ldg(&g_csr[i + 1]);
        int n2 = __ldg(&g_csr[i + 2]);
        int n3 = __ldg(&g_csr[i + 3]);
        uint2 u0 = __ldg(&xv[(size_t)n0 * 32 + lane]);
        uint2 u1 = __ldg(&xv[(size_t)n1 * 32 + lane]);
        uint2 u2 = __ldg(&xv[(size_t)n2 * 32 + lane]);
        uint2 u3 = __ldg(&xv[(size_t)n3 * 32 + lane]);
        tree4_acc(acc, u0, u1, u2, u3);
    }
    for (; i < e; i++) {
        int nb = __ldg(&g_csr[i]);
        float4 v = h4_to_f4(__ldg(&xv[(size_t)nb * 32 + lane]));
        acc.x += v.x; acc.y += v.y; acc.z += v.z; acc.w += v.w;
    }
    __half2 p0 = __floats2half2_rn(acc.x, acc.y);
    __half2 p1 = __floats2half2_rn(acc.z, acc.w);
    uint2 o;
    o.x = *reinterpret_cast<unsigned*>(&p0);
    o.y = *reinterpret_cast<unsigned*>(&p1);
    ((uint2*)out)[(size_t)w * 32 + lane] = o;
}

// ---------------- fp16 tensor-core GEMM, M-tile 128 (A always fp16) ----------
// PRE_BN:  per-column affine + relu applied while staging A
// OUT_RELU / STATS / OUT_HALF as before. Accumulation fp32.
// STATS also performs the BN finalize in the LAST CTA (ticket), writing
// g_scale/g_shift — removes the separate bnfinalize launches.
template <bool PRE_BN, bool OUT_RELU, bool STATS, bool OUT_HALF>
__global__ __launch_bounds__(256) void gemm128h_kernel(
    const __half* __restrict__ A, const __half* __restrict__ WT,
    const float* __restrict__ bias,
    const float* __restrict__ scale, const float* __restrict__ shift,
    const float* __restrict__ gamma, const float* __restrict__ beta,
    unsigned* ticket,
    float* __restrict__ C, __half* __restrict__ Ch, int M) {
    extern __shared__ float smemf[];
    unsigned* As = (unsigned*)smemf;          // MT x LDH (uint32 = 2 halves)
    unsigned* Bs = As + MT * LDH;             // 128 x LDH (n-major: [n][k])
    int tid = threadIdx.x;
    int r0 = blockIdx.x * MT;

    // Bs: coalesced uint4 copy of pre-transposed fp16 W^T (2048 uint4)
    #pragma unroll
    for (int i = 0; i < 8; i++) {
        int idx4 = tid + i * 256;        // 0..2047
        uint4 u = ((const uint4*)WT)[idx4];
        int n = idx4 >> 4, koff = (idx4 & 15) * 4;
        *(uint4*)&Bs[n * LDH + koff] = u;
    }
    // As: fp16 rows (2048 uint4); optional fused BN affine + relu
    #pragma unroll
    for (int i = 0; i < 8; i++) {
        int idx4 = tid + i * 256;        // 0..2047
        int row = idx4 >> 4, q4 = idx4 & 15;
        uint4 u = make_uint4(0u, 0u, 0u, 0u);
        if (r0 + row < M)
            u = ((const uint4*)(A + (size_t)(r0 + row) * 128))[q4];
        if (PRE_BN) {
            int c = q4 * 8;
            float2 f0 = __half22float2(*(__half2*)&u.x);
            float2 f1 = __half22float2(*(__half2*)&u.y);
            float2 f2 = __half22float2(*(__half2*)&u.z);
            float2 f3 = __half22float2(*(__half2*)&u.w);
            f0.x = fmaxf(f0.x * __ldg(&scale[c + 0]) + __ldg(&shift[c + 0]), 0.f);
            f0.y = fmaxf(f0.y * __ldg(&scale[c + 1]) + __ldg(&shift[c + 1]), 0.f);
            f1.x = fmaxf(f1.x * __ldg(&scale[c + 2]) + __ldg(&shift[c + 2]), 0.f);
            f1.y = fmaxf(f1.y * __ldg(&scale[c + 3]) + __ldg(&shift[c + 3]), 0.f);
            f2.x = fmaxf(f2.x * __ldg(&scale[c + 4]) + __ldg(&shift[c + 4]), 0.f);
            f2.y = fmaxf(f2.y * __ldg(&scale[c + 5]) + __ldg(&shift[c + 5]), 0.f);
            f3.x = fmaxf(f3.x * __ldg(&scale[c + 6]) + __ldg(&shift[c + 6]), 0.f);
            f3.y = fmaxf(f3.y * __ldg(&scale[c + 7]) + __ldg(&shift[c + 7]), 0.f);
            __half2 p0 = __floats2half2_rn(f0.x, f0.y);
            __half2 p1 = __floats2half2_rn(f1.x, f1.y);
            __half2 p2 = __floats2half2_rn(f2.x, f2.y);
            __half2 p3 = __floats2half2_rn(f3.x, f3.y);
            u.x = *reinterpret_cast<unsigned*>(&p0);
            u.y = *reinterpret_cast<unsigned*>(&p1);
            u.z = *reinterpret_cast<unsigned*>(&p2);
            u.w = *reinterpret_cast<unsigned*>(&p3);
        }
        *(uint4*)&As[row * LDH + q4 * 4] = u;
    }
    __syncthreads();

    int wid = tid >> 5, lane = tid & 31;
    int wm = wid >> 2, wn = wid & 3;     // 2 (M) x 4 (N) warps; warp tile 64x32
    int gid = lane >> 2, qid = lane & 3;

    float c[4][4][4];
    #pragma unroll
    for (int mi = 0; mi < 4; mi++)
        #pragma unroll
        for (int ni = 0; ni < 4; ni++)
            #pragma unroll
            for (int j = 0; j < 4; j++) c[mi][ni][j] = 0.f;

    #pragma unroll
    for (int kk = 0; kk < 8; kk++) {
        int k0 = kk * 8;                 // uint32 offset = 16 halves
        unsigned a[4][4];
        #pragma unroll
        for (int mi = 0; mi < 4; mi++) {
            int r = wm * 64 + mi * 16 + gid;
            a[mi][0] = As[r * LDH + k0 + qid];
            a[mi][1] = As[(r + 8) * LDH + k0 + qid];
            a[mi][2] = As[r * LDH + k0 + 4 + qid];
            a[mi][3] = As[(r + 8) * LDH + k0 + 4 + qid];
        }
        unsigned b[4][2];
        #pragma unroll
        for (int ni = 0; ni < 4; ni++) {
            int n = wn * 32 + ni * 8 + gid;
            b[ni][0] = Bs[n * LDH + k0 + qid];
            b[ni][1] = Bs[n * LDH + k0 + 4 + qid];
        }
        #pragma unroll
        for (int mi = 0; mi < 4; mi++)
            #pragma unroll
            for (int ni = 0; ni < 4; ni++)
                mma_f16(c[mi][ni], a[mi], b[ni]);
    }

    // ---- epilogue: bias (+relu), stores; optional column-stat partials ----
    float sarr[8], qarr[8];
    if (STATS) {
        #pragma unroll
        for (int t = 0; t < 8; t++) { sarr[t] = 0.f; qarr[t] = 0.f; }
    }
    #pragma unroll
    for (int ni = 0; ni < 4; ni++) {
        int col = wn * 32 + ni * 8 + 2 * qid;
        float b0 = __ldg(&bias[col]);
        float b1 = __ldg(&bias[col + 1]);
        #pragma unroll
        for (int mi = 0; mi < 4; mi++) {
            int gr = r0 + wm * 64 + mi * 16 + gid;
            float o0 = c[mi][ni][0] + b0;
            float o1 = c[mi][ni][1] + b1;
            float o2 = c[mi][ni][2] + b0;
            float o3 = c[mi][ni][3] + b1;
            if (OUT_RELU) {
                o0 = fmaxf(o0, 0.f); o1 = fmaxf(o1, 0.f);
                o2 = fmaxf(o2, 0.f); o3 = fmaxf(o3, 0.f);
            }
            if (gr < M) {
                if (OUT_HALF)
                    ((__half2*)Ch)[(size_t)gr * 64 + (col >> 1)] = __floats2half2_rn(o0, o1);
                else
                    *(float2*)(C + (size_t)gr * 128 + col) = make_float2(o0, o1);
                if (STATS) {
                    sarr[ni * 2 + 0] += o0; qarr[ni * 2 + 0] += o0 * o0;
                    sarr[ni * 2 + 1] += o1; qarr[ni * 2 + 1] += o1 * o1;
                }
            }
            if (gr + 8 < M) {
                if (OUT_HALF)
                    ((__half2*)Ch)[(size_t)(gr + 8) * 64 + (col >> 1)] = __floats2half2_rn(o2, o3);
                else
                    *(float2*)(C + (size_t)(gr + 8) * 128 + col) = make_float2(o2, o3);
                if (STATS) {
                    sarr[ni * 2 + 0] += o2; qarr[ni * 2 + 0] += o2 * o2;
                    sarr[ni * 2 + 1] += o3; qarr[ni * 2 + 1] += o3 * o3;
                }
            }
        }
    }

    if (STATS) {
        // reduce over gid lanes (same qid): butterfly masks 4,8,16 (deterministic)
        #pragma unroll
        for (int t = 0; t < 8; t++) {
            #pragma unroll
            for (int m = 4; m <= 16; m <<= 1) {
                sarr[t] += __shfl_xor_sync(0xffffffffu, sarr[t], m);
                qarr[t] += __shfl_xor_sync(0xffffffffu, qarr[t], m);
            }
        }
        __syncthreads();                 // done reading As/Bs; reuse as scratch
        float* sS = smemf;               // [2][128]
        float* sQ = smemf + 256;         // [2][128]
        if (gid == 0) {
            #pragma unroll
            for (int t = 0; t < 8; t++) {
                int col = wn * 32 + (t >> 1) * 8 + 2 * qid + (t & 1);
                sS[wm * 128 + col] = sarr[t];
                sQ[wm * 128 + col] = qarr[t];
            }
        }
        __syncthreads();
        if (tid < 128) {
            g_psum[blockIdx.x * 128 + tid] = sS[tid] + sS[128 + tid];
            g_psq[blockIdx.x * 128 + tid] = sQ[tid] + sQ[128 + tid];
        }

        // ---- last-CTA BN finalize (ticket; deterministic fixed-order tree) ----
        __threadfence();
        __shared__ unsigned is_last;
        if (tid == 0) is_last = (atomicAdd(ticket, 1u) == (unsigned)(GB1 - 1));
        __syncthreads();
        if (is_last) {
            int cc = tid & 127, chunk = tid >> 7;    // 2 chunks x 128 cols
            float s = 0.f, q = 0.f;
            for (int i = chunk; i < GB1; i += 2) {
                s += g_psum[i * 128 + cc];
                q += g_psq[i * 128 + cc];
            }
            sS[chunk * 128 + cc] = s;
            sQ[chunk * 128 + cc] = q;
            __syncthreads();
            if (tid < 128) {
                float S = sS[cc] + sS[128 + cc];
                float Qv = sQ[cc] + sQ[128 + cc];
                float mu = S / (float)NN;
                float var = Qv / (float)NN - mu * mu;
                float sc = __ldg(&gamma[cc]) * rsqrtf(var + BN_EPS);
                g_scale[cc] = sc;
                g_shift[cc] = __ldg(&beta[cc]) - mu * sc;
            }
        }
    }
}

// ---------------- fused pooling + head MLP (block per graph) ----------------
__device__ __forceinline__ int lower_bound_batch(const void* batch, int key) {
    int lo = 0, hi = NN;
    while (lo < hi) {
        int mid = (lo + hi) >> 1;
        int v = load_idx(batch, mid);
        if (v < key) lo = mid + 1; else hi = mid;
    }
    return lo;
}

__global__ void poolhead_kernel(const float* __restrict__ x, const void* batch,
                                const float* __restrict__ W1,
                                const float* __restrict__ b1,
                                const float* __restrict__ W2,
                                const float* __restrict__ b2,
                                float* __restrict__ out) {
    __shared__ float pr[128];
    __shared__ float h1[128];
    __shared__ int seg[2];
    int g = blockIdx.x;
    int c = threadIdx.x;
    if (c < 2) seg[c] = lower_bound_batch(batch, g + c);
    __syncthreads();
    float acc = 0.f;
    for (int r = seg[0]; r < seg[1]; r++)
        acc += x[(size_t)r * 128 + c];
    pr[c] = acc;
    __syncthreads();
    float s = b1[c];
    #pragma unroll 8
    for (int k = 0; k < 128; k++) s += pr[k] * W1[k * 128 + c];
    h1[c] = fmaxf(s, 0.f);
    __syncthreads();
    if (c < NC) {
        float o = b2[c];
        #pragma unroll 8
        for (int k = 0; k < 128; k++) o += h1[k] * W2[k * NC + c];
        out[g * NC + c] = o;
    }
}

// ---------------- launcher ----------------
extern "C" void kernel_launch(void* const* d_in, const int* in_sizes, int n_in,
                              void* d_out, int out_size) {
    const float* x       = (const float*)d_in[0];
    const void*  ei      = d_in[1];
    const void*  batch   = d_in[2];
    const float* conv_W1 = (const float*)d_in[3];
    const float* conv_b1 = (const float*)d_in[4];
    const float* conv_g  = (const float*)d_in[5];
    const float* conv_bt = (const float*)d_in[6];
    const float* conv_W2 = (const float*)d_in[7];
    const float* conv_b2 = (const float*)d_in[8];
    const float* head_W1 = (const float*)d_in[9];
    const float* head_b1 = (const float*)d_in[10];
    const float* head_W2 = (const float*)d_in[11];
    const float* head_b2 = (const float*)d_in[12];
    float* out = (float*)d_out;

    float *P, *scale, *shift;
    __half *Q, *R, *H, *WT;
    unsigned *ticket;
    cudaGetSymbolAddress((void**)&P, g_P);
    cudaGetSymbolAddress((void**)&Q, g_Q);
    cudaGetSymbolAddress((void**)&R, g_R);
    cudaGetSymbolAddress((void**)&H, g_H);
    cudaGetSymbolAddress((void**)&WT, g_WT);
    cudaGetSymbolAddress((void**)&scale, g_scale);
    cudaGetSymbolAddress((void**)&shift, g_shift);
    cudaGetSymbolAddress((void**)&ticket, g_ticket);

    const int SMEM = (MT + 128) * LDH * 4;   // 69632 B
    cudaFuncSetAttribute(gemm128h_kernel<false, false, true, true>,
                         cudaFuncAttributeMaxDynamicSharedMemorySize, SMEM);
    cudaFuncSetAttribute(gemm128h_kernel<true, true, false, true>,
                         cudaFuncAttributeMaxDynamicSharedMemorySize, SMEM);
    cudaFuncSetAttribute(gemm128h_kernel<true, true, false, false>,
                         cudaFuncAttributeMaxDynamicSharedMemorySize, SMEM);

    // launch 0: zero counts/tickets + x->fp16 + detect
    zero_prep_kernel<<<(NN * FD / 2 + 255) / 256, 256>>>(
        (const unsigned*)ei, (const float2*)x, (__half2*)H);
    // launch 1: degree count + W transpose
    count_kernel<<<NE / 256 + 160, 256>>>(ei, conv_W1, conv_W2);
    scan_reduce_kernel<<<SCAN_B, 1024>>>();
    scan_final_kernel<<<SCAN_B, 1024>>>();
    fill_kernel<<<NE / 256, 256>>>(ei);

    for (int l = 0; l < NL; l++) {
        // R = fp16( H + sum_neighbors H )  [HADD2 trees, fp32 carry, MLP-8]
        agg_kernel<<<(NN * 32 + 255) / 256, 256>>>(H, R);
        // Q = fp16( R @ W1 + b1 ), fused fp32 stats + last-CTA BN finalize
        gemm128h_kernel<false, false, true, true><<<GB1, 256, SMEM>>>(
            R, WT + (size_t)l * 16384, conv_b1 + l * FD,
            nullptr, nullptr, conv_g + l * FD, conv_bt + l * FD, ticket + l,
            nullptr, Q, NN);
        // out = relu( relu(BN(Q)) @ W2 + b2 ): fp16 for next gather, fp32 last
        if (l < NL - 1) {
            gemm128h_kernel<true, true, false, true><<<GB1, 256, SMEM>>>(
                Q, WT + (size_t)(5 + l) * 16384, conv_b2 + l * FD,
                scale, shift, nullptr, nullptr, nullptr,
                nullptr, H, NN);
        } else {
            gemm128h_kernel<true, true, false, false><<<GB1, 256, SMEM>>>(
                Q, WT + (size_t)(5 + l) * 16384, conv_b2 + l * FD,
                scale, shift, nullptr, nullptr, nullptr,
                P, nullptr, NN);
        }
    }

    poolhead_kernel<<<NG, 128>>>(P, batch, head_W1, head_b1, head_W2, head_b2, out);
}

// round 14
// speedup vs baseline: 1.0815x; 1.0815x over previous
#include <cuda_runtime.h>
#include <cuda_fp16.h>
#include <cstdint>

#define NN 100000
#define NE 1600000
#define FD 128
#define NG 512
#define NC 10
#define NL 5
#define BN_EPS 1e-5f
#define SCAN_B 98                  // ceil(NN/1024)
#define LDH 68                     // padded smem stride (uint32 = 2 halves)
#define MT 128                     // GEMM M-tile
#define GB1 ((NN + MT - 1) / MT)   // 782 GEMM blocks

// ---------------- scratch (device globals; no allocs allowed) ----------------
__device__ __half   g_Q[NN * FD];        // GEMM1 output (fp16, pre-BN)
__device__ __half   g_R[NN * FD];        // agg output / final features (fp16)
__device__ __half   g_H[NN * FD];        // fp16 features for gather
__device__ __half   g_WT[10 * FD * FD];  // pre-transposed fp16 weights [mat][n][k]
__device__ float    g_psum[GB1 * FD];
__device__ float    g_psq[GB1 * FD];
__device__ float    g_scale[FD];
__device__ float    g_shift[FD];
__device__ int      g_cnt[NN];
__device__ int      g_off[NN + 1];
__device__ int      g_cur[NN];
__device__ int      g_csr[NE];
__device__ int      g_bsum[SCAN_B];
__device__ int      g_is64;

__device__ __forceinline__ int load_idx(const void* p, long long i) {
    if (g_is64) return (int)((const long long*)p)[i];
    return ((const int*)p)[i];
}

// ---------------- launch 0: zero counts + x->fp16 + index-width detect ---------
__global__ void zero_prep_kernel(const unsigned* ei_words,
                                 const float2* __restrict__ x,
                                 __half2* __restrict__ h) {
    int i = blockIdx.x * 256 + threadIdx.x;
    if (i < NN * FD / 2) {
        float2 v = x[i];
        h[i] = __floats2half2_rn(v.x, v.y);
    }
    if (i < NN) g_cnt[i] = 0;
    if (i == 0) {
        int is64 = 1;
        for (int k = 1; k < 64; k++) {
            if (ei_words[2 * k + 1] != 0u) { is64 = 0; break; }
        }
        g_is64 = is64;
    }
}

// ---------------- launch 1: degree count + W transpose->fp16 -------------------
__global__ void count_kernel(const void* ei,
                             const float* __restrict__ W1,
                             const float* __restrict__ W2) {
    int b = blockIdx.x;
    if (b < NE / 256) {
        int e = b * 256 + threadIdx.x;
        int d = load_idx(ei, (long long)NE + e);
        atomicAdd(&g_cnt[d], 1);
    } else {
        int wb = b - NE / 256;              // 0..159
        int m = wb >> 4, s = wb & 15;
        const float* W = (m < 5) ? W1 + (size_t)m * FD * FD
                                 : W2 + (size_t)(m - 5) * FD * FD;
        int task = s * 256 + threadIdx.x;   // 0..4095 (4 k-values at one n)
        int n = task >> 5, k0 = (task & 31) * 4;
        __half2 p0 = __floats2half2_rn(__ldg(&W[(k0 + 0) * 128 + n]),
                                       __ldg(&W[(k0 + 1) * 128 + n]));
        __half2 p1 = __floats2half2_rn(__ldg(&W[(k0 + 2) * 128 + n]),
                                       __ldg(&W[(k0 + 3) * 128 + n]));
        uint2 o;
        o.x = *reinterpret_cast<unsigned*>(&p0);
        o.y = *reinterpret_cast<unsigned*>(&p1);
        *(uint2*)&g_WT[(size_t)m * 16384 + n * 128 + k0] = o;
    }
}

__global__ void scan_reduce_kernel() {
    int i = blockIdx.x * 1024 + threadIdx.x;
    int v = (i < NN) ? g_cnt[i] : 0;
    __shared__ int ws[32];
    int lane = threadIdx.x & 31, wid = threadIdx.x >> 5;
    #pragma unroll
    for (int d = 16; d > 0; d >>= 1) v += __shfl_down_sync(0xffffffffu, v, d);
    if (lane == 0) ws[wid] = v;
    __syncthreads();
    if (wid == 0) {
        int t = ws[lane];
        #pragma unroll
        for (int d = 16; d > 0; d >>= 1) t += __shfl_down_sync(0xffffffffu, t, d);
        if (lane == 0) g_bsum[blockIdx.x] = t;
    }
}

// block-local scan + serial per-block prefix of g_bsum
__global__ void scan_final_kernel() {
    __shared__ int wsum[32];
    __shared__ int carry;
    int tid = threadIdx.x, lane = tid & 31, wid = tid >> 5;
    if (tid == 0) {
        int acc = 0;
        for (int j = 0; j < blockIdx.x; j++) acc += g_bsum[j];
        carry = acc;
        if (blockIdx.x == SCAN_B - 1) {
            int tot = acc;
            for (int j = blockIdx.x; j < SCAN_B; j++) tot += g_bsum[j];
            g_off[NN] = tot;
        }
    }
    int i = blockIdx.x * 1024 + tid;
    int v = (i < NN) ? g_cnt[i] : 0;
    int incl = v;
    #pragma unroll
    for (int d = 1; d < 32; d <<= 1) {
        int t = __shfl_up_sync(0xffffffffu, incl, d);
        if (lane >= d) incl += t;
    }
    if (lane == 31) wsum[wid] = incl;
    __syncthreads();
    if (wid == 0) {
        int wv = wsum[lane];
        int wincl = wv;
        #pragma unroll
        for (int d = 1; d < 32; d <<= 1) {
            int t = __shfl_up_sync(0xffffffffu, wincl, d);
            if (lane >= d) wincl += t;
        }
        wsum[lane] = wincl - wv;
    }
    __syncthreads();
    if (i < NN) {
        int off = carry + wsum[wid] + incl - v;
        g_off[i] = off;
        g_cur[i] = off;
    }
}

__global__ void fill_kernel(const void* ei) {
    int e = blockIdx.x * blockDim.x + threadIdx.x;
    if (e < NE) {
        int s = load_idx(ei, e);
        int d = load_idx(ei, (long long)NE + e);
        int pos = atomicAdd(&g_cur[d], 1);
        g_csr[pos] = s;
    }
}

// ---------------- fp16 mma helper ----------------
__device__ __forceinline__ void mma_f16(float* c, const unsigned* a, const unsigned* b) {
    asm volatile(
        "mma.sync.aligned.m16n8k16.row.col.f32.f16.f16.f32 "
        "{%0,%1,%2,%3}, {%4,%5,%6,%7}, {%8,%9}, {%0,%1,%2,%3};"
        : "+f"(c[0]), "+f"(c[1]), "+f"(c[2]), "+f"(c[3])
        : "r"(a[0]), "r"(a[1]), "r"(a[2]), "r"(a[3]), "r"(b[0]), "r"(b[1]));
}

// ---------------- edge aggregation (fp16 in, HADD2 tree, fp32 acc, fp16 out) --
__device__ __forceinline__ float4 h4_to_f4(uint2 u) {
    __half2 h0 = *(__half2*)&u.x;
    __half2 h1 = *(__half2*)&u.y;
    float2 f0 = __half22float2(h0);
    float2 f1 = __half22float2(h1);
    return make_float4(f0.x, f0.y, f1.x, f1.y);
}

__global__ __launch_bounds__(256) void agg_kernel(const __half* __restrict__ xh,
                                                  __half* __restrict__ out) {
    int w = (blockIdx.x * blockDim.x + threadIdx.x) >> 5;
    int lane = threadIdx.x & 31;
    if (w >= NN) return;
    const uint2* xv = (const uint2*)xh;       // 32 uint2 per row (128 halves)
    float4 acc = h4_to_f4(__ldg(&xv[(size_t)w * 32 + lane]));
    int s = g_off[w], e = g_off[w + 1];
    int i = s;
    for (; i + 4 <= e; i += 4) {
        int n0 = __ldg(&g_csr[i + 0]);
        int n1 = __ldg(&g_csr[i + 1]);
        int n2 = __ldg(&g_csr[i + 2]);
        int n3 = __ldg(&g_csr[i + 3]);
        uint2 u0 = __ldg(&xv[(size_t)n0 * 32 + lane]);
        uint2 u1 = __ldg(&xv[(size_t)n1 * 32 + lane]);
        uint2 u2 = __ldg(&xv[(size_t)n2 * 32 + lane]);
        uint2 u3 = __ldg(&xv[(size_t)n3 * 32 + lane]);
        __half2 plo = __hadd2(__hadd2(*(__half2*)&u0.x, *(__half2*)&u1.x),
                              __hadd2(*(__half2*)&u2.x, *(__half2*)&u3.x));
        __half2 phi = __hadd2(__hadd2(*(__half2*)&u0.y, *(__half2*)&u1.y),
                              __hadd2(*(__half2*)&u2.y, *(__half2*)&u3.y));
        float2 flo = __half22float2(plo);
        float2 fhi = __half22float2(phi);
        acc.x += flo.x; acc.y += flo.y; acc.z += fhi.x; acc.w += fhi.y;
    }
    for (; i < e; i++) {
        int nb = __ldg(&g_csr[i]);
        float4 v = h4_to_f4(__ldg(&xv[(size_t)nb * 32 + lane]));
        acc.x += v.x; acc.y += v.y; acc.z += v.z; acc.w += v.w;
    }
    __half2 p0 = __floats2half2_rn(acc.x, acc.y);
    __half2 p1 = __floats2half2_rn(acc.z, acc.w);
    uint2 o;
    o.x = *reinterpret_cast<unsigned*>(&p0);
    o.y = *reinterpret_cast<unsigned*>(&p1);
    ((uint2*)out)[(size_t)w * 32 + lane] = o;
}

// ---------------- fp16 tensor-core GEMM, M-tile 128 (A always fp16) ----------
// PRE_BN:  per-column affine + relu applied while staging A
// OUT_RELU / STATS as before; output always fp16 to Ch. Accumulation fp32.
template <bool PRE_BN, bool OUT_RELU, bool STATS>
__global__ __launch_bounds__(256) void gemm128h_kernel(
    const __half* __restrict__ A, const __half* __restrict__ WT,
    const float* __restrict__ bias,
    const float* __restrict__ scale, const float* __restrict__ shift,
    __half* __restrict__ Ch, int M) {
    extern __shared__ float smemf[];
    unsigned* As = (unsigned*)smemf;          // MT x LDH (uint32 = 2 halves)
    unsigned* Bs = As + MT * LDH;             // 128 x LDH (n-major: [n][k])
    int tid = threadIdx.x;
    int r0 = blockIdx.x * MT;

    // Bs: coalesced uint4 copy of pre-transposed fp16 W^T (2048 uint4)
    #pragma unroll
    for (int i = 0; i < 8; i++) {
        int idx4 = tid + i * 256;        // 0..2047
        uint4 u = ((const uint4*)WT)[idx4];
        int n = idx4 >> 4, koff = (idx4 & 15) * 4;
        *(uint4*)&Bs[n * LDH + koff] = u;
    }
    // As: fp16 rows (2048 uint4); optional fused BN affine + relu
    #pragma unroll
    for (int i = 0; i < 8; i++) {
        int idx4 = tid + i * 256;        // 0..2047
        int row = idx4 >> 4, q4 = idx4 & 15;
        uint4 u = make_uint4(0u, 0u, 0u, 0u);
        if (r0 + row < M)
            u = ((const uint4*)(A + (size_t)(r0 + row) * 128))[q4];
        if (PRE_BN) {
            int c = q4 * 8;
            float2 f0 = __half22float2(*(__half2*)&u.x);
            float2 f1 = __half22float2(*(__half2*)&u.y);
            float2 f2 = __half22float2(*(__half2*)&u.z);
            float2 f3 = __half22float2(*(__half2*)&u.w);
            f0.x = fmaxf(f0.x * __ldg(&scale[c + 0]) + __ldg(&shift[c + 0]), 0.f);
            f0.y = fmaxf(f0.y * __ldg(&scale[c + 1]) + __ldg(&shift[c + 1]), 0.f);
            f1.x = fmaxf(f1.x * __ldg(&scale[c + 2]) + __ldg(&shift[c + 2]), 0.f);
            f1.y = fmaxf(f1.y * __ldg(&scale[c + 3]) + __ldg(&shift[c + 3]), 0.f);
            f2.x = fmaxf(f2.x * __ldg(&scale[c + 4]) + __ldg(&shift[c + 4]), 0.f);
            f2.y = fmaxf(f2.y * __ldg(&scale[c + 5]) + __ldg(&shift[c + 5]), 0.f);
            f3.x = fmaxf(f3.x * __ldg(&scale[c + 6]) + __ldg(&shift[c + 6]), 0.f);
            f3.y = fmaxf(f3.y * __ldg(&scale[c + 7]) + __ldg(&shift[c + 7]), 0.f);
            __half2 p0 = __floats2half2_rn(f0.x, f0.y);
            __half2 p1 = __floats2half2_rn(f1.x, f1.y);
            __half2 p2 = __floats2half2_rn(f2.x, f2.y);
            __half2 p3 = __floats2half2_rn(f3.x, f3.y);
            u.x = *reinterpret_cast<unsigned*>(&p0);
            u.y = *reinterpret_cast<unsigned*>(&p1);
            u.z = *reinterpret_cast<unsigned*>(&p2);
            u.w = *reinterpret_cast<unsigned*>(&p3);
        }
        *(uint4*)&As[row * LDH + q4 * 4] = u;
    }
    __syncthreads();

    int wid = tid >> 5, lane = tid & 31;
    int wm = wid >> 2, wn = wid & 3;     // 2 (M) x 4 (N) warps; warp tile 64x32
    int gid = lane >> 2, qid = lane & 3;

    float c[4][4][4];
    #pragma unroll
    for (int mi = 0; mi < 4; mi++)
        #pragma unroll
        for (int ni = 0; ni < 4; ni++)
            #pragma unroll
            for (int j = 0; j < 4; j++) c[mi][ni][j] = 0.f;

    #pragma unroll
    for (int kk = 0; kk < 8; kk++) {
        int k0 = kk * 8;                 // uint32 offset = 16 halves
        unsigned a[4][4];
        #pragma unroll
        for (int mi = 0; mi < 4; mi++) {
            int r = wm * 64 + mi * 16 + gid;
            a[mi][0] = As[r * LDH + k0 + qid];
            a[mi][1] = As[(r + 8) * LDH + k0 + qid];
            a[mi][2] = As[r * LDH + k0 + 4 + qid];
            a[mi][3] = As[(r + 8) * LDH + k0 + 4 + qid];
        }
        unsigned b[4][2];
        #pragma unroll
        for (int ni = 0; ni < 4; ni++) {
            int n = wn * 32 + ni * 8 + gid;
            b[ni][0] = Bs[n * LDH + k0 + qid];
            b[ni][1] = Bs[n * LDH + k0 + 4 + qid];
        }
        #pragma unroll
        for (int mi = 0; mi < 4; mi++)
            #pragma unroll
            for (int ni = 0; ni < 4; ni++)
                mma_f16(c[mi][ni], a[mi], b[ni]);
    }

    // ---- epilogue: bias (+relu), fp16 stores; optional column-stat partials ----
    float sarr[8], qarr[8];
    if (STATS) {
        #pragma unroll
        for (int t = 0; t < 8; t++) { sarr[t] = 0.f; qarr[t] = 0.f; }
    }
    #pragma unroll
    for (int ni = 0; ni < 4; ni++) {
        int col = wn * 32 + ni * 8 + 2 * qid;
        float b0 = __ldg(&bias[col]);
        float b1 = __ldg(&bias[col + 1]);
        #pragma unroll
        for (int mi = 0; mi < 4; mi++) {
            int gr = r0 + wm * 64 + mi * 16 + gid;
            float o0 = c[mi][ni][0] + b0;
            float o1 = c[mi][ni][1] + b1;
            float o2 = c[mi][ni][2] + b0;
            float o3 = c[mi][ni][3] + b1;
            if (OUT_RELU) {
                o0 = fmaxf(o0, 0.f); o1 = fmaxf(o1, 0.f);
                o2 = fmaxf(o2, 0.f); o3 = fmaxf(o3, 0.f);
            }
            if (gr < M) {
                ((__half2*)Ch)[(size_t)gr * 64 + (col >> 1)] = __floats2half2_rn(o0, o1);
                if (STATS) {
                    sarr[ni * 2 + 0] += o0; qarr[ni * 2 + 0] += o0 * o0;
                    sarr[ni * 2 + 1] += o1; qarr[ni * 2 + 1] += o1 * o1;
                }
            }
            if (gr + 8 < M) {
                ((__half2*)Ch)[(size_t)(gr + 8) * 64 + (col >> 1)] = __floats2half2_rn(o2, o3);
                if (STATS) {
                    sarr[ni * 2 + 0] += o2; qarr[ni * 2 + 0] += o2 * o2;
                    sarr[ni * 2 + 1] += o3; qarr[ni * 2 + 1] += o3 * o3;
                }
            }
        }
    }

    if (STATS) {
        // reduce over gid lanes (same qid): butterfly masks 4,8,16 (deterministic)
        #pragma unroll
        for (int t = 0; t < 8; t++) {
            #pragma unroll
            for (int m = 4; m <= 16; m <<= 1) {
                sarr[t] += __shfl_xor_sync(0xffffffffu, sarr[t], m);
                qarr[t] += __shfl_xor_sync(0xffffffffu, qarr[t], m);
            }
        }
        __syncthreads();                 // done reading As/Bs; reuse as scratch
        float* sS = smemf;               // [2][128]
        float* sQ = smemf + 256;         // [2][128]
        if (gid == 0) {
            #pragma unroll
            for (int t = 0; t < 8; t++) {
                int col = wn * 32 + (t >> 1) * 8 + 2 * qid + (t & 1);
                sS[wm * 128 + col] = sarr[t];
                sQ[wm * 128 + col] = qarr[t];
            }
        }
        __syncthreads();
        if (tid < 128) {
            g_psum[blockIdx.x * 128 + tid] = sS[tid] + sS[128 + tid];
            g_psq[blockIdx.x * 128 + tid] = sQ[tid] + sQ[128 + tid];
        }
    }
}

// ---------------- BN finalize: 128 blocks, one column each (deterministic) ----
__global__ void bnfinalize_kernel(const float* __restrict__ gamma,
                                  const float* __restrict__ beta) {
    __shared__ float ss[128];
    __shared__ float qq[128];
    int c = blockIdx.x;              // column
    int t = threadIdx.x;             // 128 threads, chunked serial reads
    float s = 0.f, q = 0.f;
    for (int i = t; i < GB1; i += 128) {
        s += g_psum[i * 128 + c];
        q += g_psq[i * 128 + c];
    }
    ss[t] = s; qq[t] = q;
    __syncthreads();
    if (t == 0) {
        float S = 0.f, Qv = 0.f;
        #pragma unroll
        for (int k = 0; k < 128; k++) { S += ss[k]; Qv += qq[k]; }
        float mu = S / (float)NN;
        float var = Qv / (float)NN - mu * mu;
        float sc = gamma[c] * rsqrtf(var + BN_EPS);
        g_scale[c] = sc;
        g_shift[c] = beta[c] - mu * sc;
    }
}

// ---------------- fused pooling (fp16 in, fp32 acc) + head MLP ----------------
__device__ __forceinline__ int lower_bound_batch(const void* batch, int key) {
    int lo = 0, hi = NN;
    while (lo < hi) {
        int mid = (lo + hi) >> 1;
        int v = load_idx(batch, mid);
        if (v < key) lo = mid + 1; else hi = mid;
    }
    return lo;
}

__global__ void poolhead_kernel(const __half* __restrict__ x, const void* batch,
                                const float* __restrict__ W1,
                                const float* __restrict__ b1,
                                const float* __restrict__ W2,
                                const float* __restrict__ b2,
                                float* __restrict__ out) {
    __shared__ float pr[128];
    __shared__ float h1[128];
    __shared__ int seg[2];
    int g = blockIdx.x;
    int c = threadIdx.x;
    if (c < 2) seg[c] = lower_bound_batch(batch, g + c);
    __syncthreads();
    float acc = 0.f;
    for (int r = seg[0]; r < seg[1]; r++)
        acc += __half2float(x[(size_t)r * 128 + c]);
    pr[c] = acc;
    __syncthreads();
    float s = b1[c];
    #pragma unroll 8
    for (int k = 0; k < 128; k++) s += pr[k] * W1[k * 128 + c];
    h1[c] = fmaxf(s, 0.f);
    __syncthreads();
    if (c < NC) {
        float o = b2[c];
        #pragma unroll 8
        for (int k = 0; k < 128; k++) o += h1[k] * W2[k * NC + c];
        out[g * NC + c] = o;
    }
}

// ---------------- launcher ----------------
extern "C" void kernel_launch(void* const* d_in, const int* in_sizes, int n_in,
                              void* d_out, int out_size) {
    const float* x       = (const float*)d_in[0];
    const void*  ei      = d_in[1];
    const void*  batch   = d_in[2];
    const float* conv_W1 = (const float*)d_in[3];
    const float* conv_b1 = (const float*)d_in[4];
    const float* conv_g  = (const float*)d_in[5];
    const float* conv_bt = (const float*)d_in[6];
    const float* conv_W2 = (const float*)d_in[7];
    const float* conv_b2 = (const float*)d_in[8];
    const float* head_W1 = (const float*)d_in[9];
    const float* head_b1 = (const float*)d_in[10];
    const float* head_W2 = (const float*)d_in[11];
    const float* head_b2 = (const float*)d_in[12];
    float* out = (float*)d_out;

    float *scale, *shift;
    __half *Q, *R, *H, *WT;
    cudaGetSymbolAddress((void**)&Q, g_Q);
    cudaGetSymbolAddress((void**)&R, g_R);
    cudaGetSymbolAddress((void**)&H, g_H);
    cudaGetSymbolAddress((void**)&WT, g_WT);
    cudaGetSymbolAddress((void**)&scale, g_scale);
    cudaGetSymbolAddress((void**)&shift, g_shift);

    const int SMEM = (MT + 128) * LDH * 4;   // 69632 B
    cudaFuncSetAttribute(gemm128h_kernel<false, false, true>,
                         cudaFuncAttributeMaxDynamicSharedMemorySize, SMEM);
    cudaFuncSetAttribute(gemm128h_kernel<true, true, false>,
                         cudaFuncAttributeMaxDynamicSharedMemorySize, SMEM);

    // launch 0: zero counts + x->fp16 + detect
    zero_prep_kernel<<<(NN * FD / 2 + 255) / 256, 256>>>(
        (const unsigned*)ei, (const float2*)x, (__half2*)H);
    // launch 1: degree count + W transpose
    count_kernel<<<NE / 256 + 160, 256>>>(ei, conv_W1, conv_W2);
    scan_reduce_kernel<<<SCAN_B, 1024>>>();
    scan_final_kernel<<<SCAN_B, 1024>>>();
    fill_kernel<<<NE / 256, 256>>>(ei);

    for (int l = 0; l < NL; l++) {
        // R = fp16( H + sum_neighbors H )  [HADD2 tree, fp32 carry, MLP-4]
        agg_kernel<<<(NN * 32 + 255) / 256, 256>>>(H, R);
        // Q = fp16( R @ W1 + b1 ), with fused fp32 column stats
        gemm128h_kernel<false, false, true><<<GB1, 256, SMEM>>>(
            R, WT + (size_t)l * 16384, conv_b1 + l * FD,
            nullptr, nullptr, Q, NN);
        bnfinalize_kernel<<<FD, 128>>>(conv_g + l * FD, conv_bt + l * FD);
        // dst = relu( relu(BN(Q)) @ W2 + b2 ), fp16:
        //   layers 0..3 -> H (next gather); last layer -> R (pooling input)
        __half* dst = (l < NL - 1) ? H : R;
        gemm128h_kernel<true, true, false><<<GB1, 256, SMEM>>>(
            Q, WT + (size_t)(5 + l) * 16384, conv_b2 + l * FD,
            scale, shift, dst, NN);
    }

    poolhead_kernel<<<NG, 128>>>(R, batch, head_W1, head_b1, head_W2, head_b2, out);
}